// round 1
// baseline (speedup 1.0000x reference)
#include <cuda_runtime.h>

// Gray-Scott residual:
//   lap(c) = [sum over 3 axes of 5-tap 4th-order stencil] / DX^2
//   u_t = (u[t+1] - u[t]) / DT  (centers only)
//   f_u = DU*lap_u - u*v^2 + FF*(1-u) - u_t
//   f_v = DV*lap_v + u*v^2 - (FF+KK)*v - v_t
//
// Input  : output (50, 2, 100, 100, 100) fp32, laplace_filter (unused: stencil hardcoded)
// Output : f_u (48,96,96,96) then f_v (48,96,96,96), concatenated.

#define T_OUT 48
#define D 96
#define IN_T_STRIDE 2000000   // 2*100*100*100
#define IN_C_STRIDE 1000000
#define IN_Y_STRIDE 10000
#define IN_X_STRIDE 100

#define N_OUT (T_OUT * D * D * D)   // 42467328

__global__ void __launch_bounds__(256) gs_loss_kernel(
    const float* __restrict__ in, float* __restrict__ out)
{
    int idx = blockIdx.x * 256 + threadIdx.x;
    if (idx >= N_OUT) return;

    int z = idx % D;
    int r = idx / D;
    int x = r % D;
    r /= D;
    int y = r % D;
    int t = r / D;

    // center input coordinate: (t, c, y+2, x+2, z+2)
    int base = t * IN_T_STRIDE + (y + 2) * IN_Y_STRIDE + (x + 2) * IN_X_STRIDE + (z + 2);
    const float* up = in + base;
    const float* vp = up + IN_C_STRIDE;

    const float cu = __ldg(up);
    const float cv = __ldg(vp);

    // +/-1 neighbors (coef 4/3) and +/-2 neighbors (coef -1/12) along each axis
    float su1 = __ldg(up - 1) + __ldg(up + 1)
              + __ldg(up - IN_X_STRIDE) + __ldg(up + IN_X_STRIDE)
              + __ldg(up - IN_Y_STRIDE) + __ldg(up + IN_Y_STRIDE);
    float su2 = __ldg(up - 2) + __ldg(up + 2)
              + __ldg(up - 2 * IN_X_STRIDE) + __ldg(up + 2 * IN_X_STRIDE)
              + __ldg(up - 2 * IN_Y_STRIDE) + __ldg(up + 2 * IN_Y_STRIDE);
    float sv1 = __ldg(vp - 1) + __ldg(vp + 1)
              + __ldg(vp - IN_X_STRIDE) + __ldg(vp + IN_X_STRIDE)
              + __ldg(vp - IN_Y_STRIDE) + __ldg(vp + IN_Y_STRIDE);
    float sv2 = __ldg(vp - 2) + __ldg(vp + 2)
              + __ldg(vp - 2 * IN_X_STRIDE) + __ldg(vp + 2 * IN_X_STRIDE)
              + __ldg(vp - 2 * IN_Y_STRIDE) + __ldg(vp + 2 * IN_Y_STRIDE);

    // next-timestep centers
    const float un = __ldg(up + IN_T_STRIDE);
    const float vn = __ldg(vp + IN_T_STRIDE);

    const float INV_DX2 = 2304.0f / 10000.0f;           // 1/DX^2, DX = 100/48
    const float C1 = 4.0f / 3.0f;
    const float C2 = -1.0f / 12.0f;
    const float C0 = -7.5f;                              // 3 * (-5/2)

    float lap_u = (C0 * cu + C1 * su1 + C2 * su2) * INV_DX2;
    float lap_v = (C0 * cv + C1 * sv1 + C2 * sv2) * INV_DX2;

    float u_t = (un - cu) * 2.0f;   // / DT, DT = 0.5
    float v_t = (vn - cv) * 2.0f;

    float uv2 = cu * cv * cv;

    float f_u = 0.2f * lap_u - uv2 + 0.025f * (1.0f - cu) - u_t;
    float f_v = 0.1f * lap_v + uv2 - 0.08f * cv - v_t;    // FF+KK = 0.08

    out[idx] = f_u;
    out[idx + N_OUT] = f_v;
}

extern "C" void kernel_launch(void* const* d_in, const int* in_sizes, int n_in,
                              void* d_out, int out_size)
{
    const float* in = (const float*)d_in[0];
    float* out = (float*)d_out;
    int blocks = (N_OUT + 255) / 256;   // 165888
    gs_loss_kernel<<<blocks, 256>>>(in, out);
}

// round 2
// speedup vs baseline: 1.0755x; 1.0755x over previous
#include <cuda_runtime.h>

// Gray-Scott residual, smem ring-buffer version.
// Input: output (50, 2, 100, 100, 100) fp32. Output: f_u(48,96,96,96) ++ f_v.
//
// Block (32 z, 8 x) marches y=0..95. Ring of 5 input y-planes in smem
// (tile 12 x-rows x 36 z-cols per channel). x/z taps from smem; y taps +
// center from a per-thread register ring.

#define TOUT 48
#define D 96
#define IN_T 2000000
#define IN_C 1000000
#define IN_Y 10000
#define IN_X 100
#define N_OUT (TOUT * D * D * D)

#define BZ 32
#define BX 8
#define TILE_Z 36   // BZ + 4 halo
#define TILE_X 12   // BX + 4 halo
#define PLANE (TILE_X * TILE_Z)   // 432

__global__ void __launch_bounds__(256) gs_loss_smem(
    const float* __restrict__ in, float* __restrict__ out)
{
    __shared__ float su[5][TILE_X][TILE_Z];
    __shared__ float sv[5][TILE_X][TILE_Z];

    const int tz = threadIdx.x;          // 0..31
    const int tx = threadIdx.y;          // 0..7
    const int tid = tx * BZ + tz;        // 0..255

    const int bz = blockIdx.x;           // 0..2
    const int bx = blockIdx.y;           // 0..11
    const int t  = blockIdx.z;           // 0..47

    const int z0 = bz * BZ;              // input z tile origin
    const int x0 = bx * BX;              // input x tile origin

    const float* base_u = in + t * IN_T;
    const float* base_v = base_u + IN_C;

    // ---- plane loader: input y-row -> ring slot s ----
    // 432 floats per channel, 256 threads -> 2 strided passes
    auto load_plane = [&](int y_in, int s) {
        const float* pu = base_u + y_in * IN_Y;
        const float* pv = base_v + y_in * IN_Y;
        {
            int i = tid;                      // pass 1 (all threads)
            int row = i / TILE_Z, col = i % TILE_Z;
            int g = (x0 + row) * IN_X + (z0 + col);
            su[s][row][col] = __ldg(pu + g);
            sv[s][row][col] = __ldg(pv + g);
        }
        {
            int i = tid + 256;                // pass 2 (176 threads)
            if (i < PLANE) {
                int row = i / TILE_Z, col = i % TILE_Z;
                int g = (x0 + row) * IN_X + (z0 + col);
                su[s][row][col] = __ldg(pu + g);
                sv[s][row][col] = __ldg(pv + g);
            }
        }
    };

    // ---- prologue: planes y_in = 0..3 into slots 0..3 ----
    load_plane(0, 0);
    load_plane(1, 1);
    load_plane(2, 2);
    load_plane(3, 3);
    __syncthreads();

    const int xc = tx + 2;
    const int zc = tz + 2;

    // register ring: centers of planes y..y+3 (input rows y..y+3)
    float ur0 = su[0][xc][zc], vr0 = sv[0][xc][zc];
    float ur1 = su[1][xc][zc], vr1 = sv[1][xc][zc];
    float ur2 = su[2][xc][zc], vr2 = sv[2][xc][zc];
    float ur3 = su[3][xc][zc], vr3 = sv[3][xc][zc];

    const int x_out = x0 + tx;
    const int z_out = z0 + tz;

    // t+1 center pointer (advances by IN_Y per y)
    const float* nup = in + (t + 1) * IN_T + 2 * IN_Y + (x_out + 2) * IN_X + (z_out + 2);
    float* ou = out + ((t * D) * D + x_out) * D + z_out;

    const float INV_DX2 = 2304.0f / 10000.0f;
    const float C1 = 4.0f / 3.0f;
    const float C2 = -1.0f / 12.0f;
    const float C0 = -7.5f;

    #pragma unroll 1
    for (int y = 0; y < D; y++) {
        const int s  = (y + 4) % 5;      // slot to overwrite (held plane y-1)
        const int sc = (y + 2) % 5;      // center plane slot

        __syncthreads();                 // everyone done reading slot s
        load_plane(y + 4, s);
        __syncthreads();                 // plane y+4 visible

        const float ur4 = su[s][xc][zc];
        const float vr4 = sv[s][xc][zc];

        const float cu = ur2;
        const float cv = vr2;

        // +/-1 taps (4/3) and +/-2 taps (-1/12)
        float su1 = su[sc][xc][zc - 1] + su[sc][xc][zc + 1]
                  + su[sc][xc - 1][zc] + su[sc][xc + 1][zc]
                  + ur1 + ur3;
        float su2 = su[sc][xc][zc - 2] + su[sc][xc][zc + 2]
                  + su[sc][xc - 2][zc] + su[sc][xc + 2][zc]
                  + ur0 + ur4;
        float sv1 = sv[sc][xc][zc - 1] + sv[sc][xc][zc + 1]
                  + sv[sc][xc - 1][zc] + sv[sc][xc + 1][zc]
                  + vr1 + vr3;
        float sv2 = sv[sc][xc][zc - 2] + sv[sc][xc][zc + 2]
                  + sv[sc][xc - 2][zc] + sv[sc][xc + 2][zc]
                  + vr0 + vr4;

        const float un = __ldg(nup + y * IN_Y);
        const float vn = __ldg(nup + y * IN_Y + IN_C);

        float lap_u = (C0 * cu + C1 * su1 + C2 * su2) * INV_DX2;
        float lap_v = (C0 * cv + C1 * sv1 + C2 * sv2) * INV_DX2;

        float u_t = (un - cu) * 2.0f;    // / DT, DT = 0.5
        float v_t = (vn - cv) * 2.0f;

        float uv2 = cu * cv * cv;

        float f_u = 0.2f * lap_u - uv2 + 0.025f * (1.0f - cu) - u_t;
        float f_v = 0.1f * lap_v + uv2 - 0.08f * cv - v_t;

        ou[y * (D * D)] = f_u;
        ou[y * (D * D) + N_OUT] = f_v;

        // rotate register ring
        ur0 = ur1; ur1 = ur2; ur2 = ur3; ur3 = ur4;
        vr0 = vr1; vr1 = vr2; vr2 = vr3; vr3 = vr4;
    }
}

extern "C" void kernel_launch(void* const* d_in, const int* in_sizes, int n_in,
                              void* d_out, int out_size)
{
    const float* in = (const float*)d_in[0];
    float* out = (float*)d_out;
    dim3 block(BZ, BX);                  // 256 threads
    dim3 grid(D / BZ, D / BX, TOUT);     // (3, 12, 48) = 1728 blocks
    gs_loss_smem<<<grid, block>>>(in, out);
}